// round 5
// baseline (speedup 1.0000x reference)
#include <cuda_runtime.h>
#include <math.h>
#include <stdint.h>

#define BATCH 4
#define CFULL 512
#define HC 256
#define HH 128
#define WW 128
#define HW (HH*WW)

__device__ float g_pool[BATCH * HC * 4];
__device__ float g_base[BATCH * 4 * CFULL];

// ---------------------------------------------------------------------------
// Kernel 1: adaptive max pool of channels 256..511 to 2x2 (float4 loads)
// ---------------------------------------------------------------------------
__global__ __launch_bounds__(256) void pool_kernel(const float* __restrict__ x) {
    int blk = blockIdx.x;
    int q  = blk & 3;
    int cc = (blk >> 2) & 255;
    int b  = blk >> 10;
    int qh = q >> 1, qw = q & 1;
    const float* xin = x + ((size_t)(b * CFULL + 256 + cc)) * HW + qh * 64 * WW + qw * 64;
    const float4* xin4 = reinterpret_cast<const float4*>(xin);

    float m = -INFINITY;
    for (int i = threadIdx.x; i < 1024; i += 256) {
        int r = i >> 4, c4 = i & 15;
        float4 v = xin4[r * 32 + c4];
        m = fmaxf(m, fmaxf(fmaxf(v.x, v.y), fmaxf(v.z, v.w)));
    }
    __shared__ float red[256];
    red[threadIdx.x] = m;
    __syncthreads();
    for (int s = 128; s > 0; s >>= 1) {
        if (threadIdx.x < s) red[threadIdx.x] = fmaxf(red[threadIdx.x], red[threadIdx.x + s]);
        __syncthreads();
    }
    if (threadIdx.x == 0) g_pool[(b * HC + cc) * 4 + q] = red[0];
}

// ---------------------------------------------------------------------------
// Kernel 2: tiny 2x2 dwconvs + base[b][q][o]
// ---------------------------------------------------------------------------
__global__ __launch_bounds__(512) void base_kernel(
    const float* __restrict__ w2, const float* __restrict__ b2,
    const float* __restrict__ w3, const float* __restrict__ b3,
    const float* __restrict__ w4, const float* __restrict__ b4,
    const float* __restrict__ wa, const float* __restrict__ ba)
{
    int b  = blockIdx.x >> 2;
    int oc = (blockIdx.x & 3) * 128;
    __shared__ float catlow[256][4];
    int t = threadIdx.x;
    if (t < 256) {
        const float* wp;
        float bias;
        if (t < 128)       { wp = w2 + t * 9;         bias = b2[t];        }
        else if (t < 192)  { wp = w3 + (t - 128) * 9; bias = b3[t - 128]; }
        else               { wp = w4 + (t - 192) * 9; bias = b4[t - 192]; }
        float i00 = g_pool[(b * HC + t) * 4 + 0];
        float i01 = g_pool[(b * HC + t) * 4 + 1];
        float i10 = g_pool[(b * HC + t) * 4 + 2];
        float i11 = g_pool[(b * HC + t) * 4 + 3];
        catlow[t][0] = i00*wp[4] + i01*wp[5] + i10*wp[7] + i11*wp[8] + bias;
        catlow[t][1] = i00*wp[3] + i01*wp[4] + i10*wp[6] + i11*wp[7] + bias;
        catlow[t][2] = i00*wp[1] + i01*wp[2] + i10*wp[4] + i11*wp[5] + bias;
        catlow[t][3] = i00*wp[0] + i01*wp[1] + i10*wp[3] + i11*wp[4] + bias;
    }
    __syncthreads();
    int o    = oc + (t >> 2);
    int part = t & 3;
    int cc0  = part * 64;
    float a0 = 0.f, a1 = 0.f, a2 = 0.f, a3 = 0.f;
    #pragma unroll 4
    for (int cc = cc0; cc < cc0 + 64; ++cc) {
        float wv = wa[o * CFULL + 256 + cc];
        a0 = fmaf(wv, catlow[cc][0], a0);
        a1 = fmaf(wv, catlow[cc][1], a1);
        a2 = fmaf(wv, catlow[cc][2], a2);
        a3 = fmaf(wv, catlow[cc][3], a3);
    }
    #pragma unroll
    for (int off = 1; off < 4; off <<= 1) {
        a0 += __shfl_xor_sync(0xffffffff, a0, off);
        a1 += __shfl_xor_sync(0xffffffff, a1, off);
        a2 += __shfl_xor_sync(0xffffffff, a2, off);
        a3 += __shfl_xor_sync(0xffffffff, a3, off);
    }
    if (part == 0) {
        float bav = ba[o];
        g_base[(b * 4 + 0) * CFULL + o] = a0 + bav;
        g_base[(b * 4 + 1) * CFULL + o] = a1 + bav;
        g_base[(b * 4 + 2) * CFULL + o] = a2 + bav;
        g_base[(b * 4 + 3) * CFULL + o] = a3 + bav;
    }
}

// ---------------------------------------------------------------------------
// Kernel 3 (fused): dwconv(a1) computed in-CTA into smem B-tile, then
// tf32 GEMM (ldmatrix + mma) + base + exact GELU + gate.
// Grid (mblock=4, row=128, batch=4). Block tile M=128 x N=128 (one image row),
// K=256. B-tile built once in smem [n=128][KPAD=260]; A (wa) double-buffered.
// ---------------------------------------------------------------------------
__device__ __forceinline__ float gelu_exact(float v) {
    return 0.5f * v * (1.0f + erff(v * 0.70710678118654752f));
}
__device__ __forceinline__ void mma_tf32(float (&d)[4], const uint32_t (&a)[4],
                                         uint32_t b0, uint32_t b1) {
    asm volatile(
        "mma.sync.aligned.m16n8k8.row.col.f32.tf32.tf32.f32 "
        "{%0,%1,%2,%3}, {%4,%5,%6,%7}, {%8,%9}, {%0,%1,%2,%3};"
        : "+f"(d[0]), "+f"(d[1]), "+f"(d[2]), "+f"(d[3])
        : "r"(a[0]), "r"(a[1]), "r"(a[2]), "r"(a[3]), "r"(b0), "r"(b1));
}
__device__ __forceinline__ void cp_async16(uint32_t dst, const void* src) {
    asm volatile("cp.async.cg.shared.global [%0], [%1], 16;" :: "r"(dst), "l"(src));
}
__device__ __forceinline__ void ldsm4(uint32_t (&r)[4], uint32_t addr) {
    asm volatile("ldmatrix.sync.aligned.m8n8.x4.shared.b16 {%0,%1,%2,%3}, [%4];"
                 : "=r"(r[0]), "=r"(r[1]), "=r"(r[2]), "=r"(r[3]) : "r"(addr));
}

#define BM 128
#define BN 128
#define BK 32
#define KPAD 260                        // Bs row stride (floats); 260%32=4 -> ldsm OK
#define BS_FLOATS (128 * KPAD)          // 33280
#define ASTRIDE 36
#define A_FLOATS (128 * ASTRIDE)        // 4608 per stage
#define STW 137                         // stage row stride; ch stride 411 (odd mod 32)
#define STAGE_FLOATS (32 * 3 * STW)     // 13152
#define UNION_FLOATS (STAGE_FLOATS > 2*A_FLOATS ? STAGE_FLOATS : 2*A_FLOATS)
#define FUSED_SMEM_BYTES ((BS_FLOATS + UNION_FLOATS) * 4)   // 185,728

__global__ __launch_bounds__(256) void fused_gemm_kernel(
    const float* __restrict__ x, const float* __restrict__ wa,
    const float* __restrict__ w1, const float* __restrict__ b1,
    float* __restrict__ out)
{
    extern __shared__ float smem[];
    float* Bs = smem;                       // [128 n][KPAD]
    float* stage = smem + BS_FLOATS;        // phase 1: [32 ch][3 rr][STW]
    uint32_t* As0 = reinterpret_cast<uint32_t*>(smem + BS_FLOATS);  // phase 2 alias

    int m0 = blockIdx.x * BM;
    int bx = blockIdx.y;                    // image row r
    int b  = blockIdx.z;
    int tid = threadIdx.x;
    int lane = tid & 31, warp = tid >> 5;
    int warpM = warp & 3;
    int warpN = warp >> 2;
    int n0 = bx * BN;

    // ======================= Phase 1: build B tile ========================
    // edge zero columns (cols 3 and 132 of each (ch,rr) row) — set once
    if (tid < 96) {
        int ch = tid / 3, rr = tid - 3 * ch;
        stage[ch * (3 * STW) + rr * STW + 3]   = 0.f;
        stage[ch * (3 * STW) + rr * STW + 132] = 0.f;
    }

    int kl = tid & 31;          // channel-in-chunk
    int ng = tid >> 5;          // col group
    int c0 = ng * 16;

    for (int cc = 0; cc < 8; ++cc) {
        __syncthreads();   // protect stage (prev chunk readers / edge-zero writers)
        // load 32 channels x 3 rows x 128 cols, coalesced float4
        #pragma unroll
        for (int j = 0; j < 12; ++j) {
            int i = tid + 256 * j;          // [0, 3072)
            int c4 = i & 31;
            int g3 = i >> 5;                // [0,96)
            int ch = g3 / 3;
            int rr = g3 - 3 * ch;
            int gr = bx + rr - 1;
            float4 v = make_float4(0.f, 0.f, 0.f, 0.f);
            if (gr >= 0 && gr < HH)
                v = *reinterpret_cast<const float4*>(
                    x + ((size_t)(b * CFULL + cc * 32 + ch)) * HW + gr * WW + c4 * 4);
            float* sp = stage + ch * (3 * STW) + rr * STW + 4 + c4 * 4;
            sp[0] = v.x; sp[1] = v.y; sp[2] = v.z; sp[3] = v.w;
        }
        __syncthreads();
        // compute conv for channel k = cc*32+kl, cols c0..c0+15
        int k = cc * 32 + kl;
        const float* wp = w1 + k * 9;
        float w00 = wp[0], w01 = wp[1], w02 = wp[2];
        float w10 = wp[3], w11 = wp[4], w12 = wp[5];
        float w20 = wp[6], w21 = wp[7], w22 = wp[8];
        float bias = b1[k];

        float rowv[3][18];
        const float* sb = stage + kl * (3 * STW);
        #pragma unroll
        for (int rr = 0; rr < 3; ++rr) {
            #pragma unroll
            for (int i = 0; i < 18; ++i)
                rowv[rr][i] = sb[rr * STW + 3 + c0 + i];
        }
        #pragma unroll
        for (int c = 0; c < 16; ++c) {
            float acc = bias;
            acc = fmaf(w00, rowv[0][c],     acc);
            acc = fmaf(w01, rowv[0][c + 1], acc);
            acc = fmaf(w02, rowv[0][c + 2], acc);
            acc = fmaf(w10, rowv[1][c],     acc);
            acc = fmaf(w11, rowv[1][c + 1], acc);
            acc = fmaf(w12, rowv[1][c + 2], acc);
            acc = fmaf(w20, rowv[2][c],     acc);
            acc = fmaf(w21, rowv[2][c + 1], acc);
            acc = fmaf(w22, rowv[2][c + 2], acc);
            Bs[(c0 + c) * KPAD + k] = acc;   // lanes write consecutive k: conflict-free
        }
    }
    __syncthreads();   // B tile complete; stage region now free for A buffers

    // ======================= Phase 2: GEMM ================================
    uint32_t as_base = (uint32_t)__cvta_generic_to_shared(As0);
    uint32_t bs_base = (uint32_t)__cvta_generic_to_shared(Bs);

    // A cp.async indices: 128 rows x 8 chunks of 16B = 1024, 4 per thread
    int rowi[4], kci[4];
    #pragma unroll
    for (int j = 0; j < 4; ++j) {
        int idx = tid + 256 * j;
        rowi[j] = idx >> 3;
        kci[j]  = (idx & 7) * 4;
    }
    auto load_A = [&](int k0, int s) {
        #pragma unroll
        for (int j = 0; j < 4; ++j) {
            const float* src = wa + (size_t)(m0 + rowi[j]) * CFULL + k0 + kci[j];
            uint32_t dst = as_base + (s * A_FLOATS + rowi[j] * ASTRIDE + kci[j]) * 4;
            cp_async16(dst, src);
        }
        asm volatile("cp.async.commit_group;" ::: "memory");
    };

    // ldmatrix per-lane offsets
    int j4 = lane >> 3;
    int a_row = ((j4 & 1) * 8) + (lane & 7);
    int a_col = (j4 >> 1) * 4;
    int b_row = ((j4 >> 1) * 8) + (lane & 7);
    int b_col = (j4 & 1) * 4;
    int aoff0 = (warpM * 32 +  0 + a_row) * ASTRIDE + a_col;
    int aoff1 = (warpM * 32 + 16 + a_row) * ASTRIDE + a_col;
    int boff[4];
    #pragma unroll
    for (int ntp = 0; ntp < 4; ++ntp)
        boff[ntp] = (warpN * 64 + ntp * 16 + b_row) * KPAD + b_col;

    float acc[2][8][4] = {};

    load_A(0, 0);

    #pragma unroll 1
    for (int it = 0; it < HC / BK; ++it) {
        asm volatile("cp.async.wait_group 0;" ::: "memory");
        __syncthreads();
        if (it < HC / BK - 1) load_A((it + 1) * BK, (it + 1) & 1);

        uint32_t aB = as_base + (it & 1) * A_FLOATS * 4;
        int kbase = it * BK;

        #pragma unroll
        for (int ks = 0; ks < 4; ++ks) {
            uint32_t af[2][4];
            ldsm4(af[0], aB + (aoff0 + ks * 8) * 4);
            ldsm4(af[1], aB + (aoff1 + ks * 8) * 4);
            #pragma unroll
            for (int ntp = 0; ntp < 4; ++ntp) {
                uint32_t bb[4];
                ldsm4(bb, bs_base + (boff[ntp] + kbase + ks * 8) * 4);
                mma_tf32(acc[0][2 * ntp    ], af[0], bb[0], bb[1]);
                mma_tf32(acc[1][2 * ntp    ], af[1], bb[0], bb[1]);
                mma_tf32(acc[0][2 * ntp + 1], af[0], bb[2], bb[3]);
                mma_tf32(acc[1][2 * ntp + 1], af[1], bb[2], bb[3]);
            }
        }
    }

    // ===================== Epilogue =====================
    int q = ((bx >= 64) ? 2 : 0) + warpN;
    const float* basep = g_base + (b * 4 + q) * CFULL;

    #pragma unroll
    for (int mt = 0; mt < 2; ++mt) {
        int mrow0 = m0 + warpM * 32 + mt * 16 + (lane >> 2);
        int mrow1 = mrow0 + 8;
        float bs0 = basep[mrow0];
        float bs1 = basep[mrow1];
        #pragma unroll
        for (int nt = 0; nt < 8; ++nt) {
            int n = n0 + warpN * 64 + nt * 8 + (lane & 3) * 2;
            size_t off0 = ((size_t)(b * CFULL + mrow0)) * HW + n;
            size_t off1 = ((size_t)(b * CFULL + mrow1)) * HW + n;
            float2 xv0 = *reinterpret_cast<const float2*>(x + off0);
            float2 xv1 = *reinterpret_cast<const float2*>(x + off1);
            float2 r0, r1;
            r0.x = gelu_exact(acc[mt][nt][0] + bs0) * xv0.x;
            r0.y = gelu_exact(acc[mt][nt][1] + bs0) * xv0.y;
            r1.x = gelu_exact(acc[mt][nt][2] + bs1) * xv1.x;
            r1.y = gelu_exact(acc[mt][nt][3] + bs1) * xv1.y;
            *reinterpret_cast<float2*>(out + off0) = r0;
            *reinterpret_cast<float2*>(out + off1) = r1;
        }
    }
}

// ---------------------------------------------------------------------------
extern "C" void kernel_launch(void* const* d_in, const int* in_sizes, int n_in,
                              void* d_out, int out_size) {
    const float* x  = (const float*)d_in[0];
    const float* w1 = (const float*)d_in[1];
    const float* b1 = (const float*)d_in[2];
    const float* w2 = (const float*)d_in[3];
    const float* b2 = (const float*)d_in[4];
    const float* w3 = (const float*)d_in[5];
    const float* b3 = (const float*)d_in[6];
    const float* w4 = (const float*)d_in[7];
    const float* b4 = (const float*)d_in[8];
    const float* wa = (const float*)d_in[9];
    const float* ba = (const float*)d_in[10];
    float* out = (float*)d_out;

    cudaFuncSetAttribute(fused_gemm_kernel,
                         cudaFuncAttributeMaxDynamicSharedMemorySize, FUSED_SMEM_BYTES);

    pool_kernel<<<BATCH * HC * 4, 256>>>(x);
    base_kernel<<<16, 512>>>(w2, b2, w3, b3, w4, b4, wa, ba);
    fused_gemm_kernel<<<dim3(CFULL / BM, HH, BATCH), 256, FUSED_SMEM_BYTES>>>(
        x, wa, w1, b1, out);
}

// round 6
// speedup vs baseline: 1.7912x; 1.7912x over previous
#include <cuda_runtime.h>
#include <math.h>
#include <stdint.h>

#define BATCH 4
#define CFULL 512
#define HC 256
#define HH 128
#define WW 128
#define HW (HH*WW)

__device__ float g_x1[BATCH * HC * HW];     // dwconv(a1), [b][k][n] layout
__device__ float g_pool[BATCH * HC * 4];
__device__ float g_base[BATCH * 4 * CFULL];

// ---------------------------------------------------------------------------
// Kernel 1: adaptive max pool of channels 256..511 to 2x2 (float4 loads)
// ---------------------------------------------------------------------------
__global__ __launch_bounds__(256) void pool_kernel(const float* __restrict__ x) {
    int blk = blockIdx.x;
    int q  = blk & 3;
    int cc = (blk >> 2) & 255;
    int b  = blk >> 10;
    int qh = q >> 1, qw = q & 1;
    const float* xin = x + ((size_t)(b * CFULL + 256 + cc)) * HW + qh * 64 * WW + qw * 64;
    const float4* xin4 = reinterpret_cast<const float4*>(xin);

    float m = -INFINITY;
    for (int i = threadIdx.x; i < 1024; i += 256) {
        int r = i >> 4, c4 = i & 15;
        float4 v = xin4[r * 32 + c4];
        m = fmaxf(m, fmaxf(fmaxf(v.x, v.y), fmaxf(v.z, v.w)));
    }
    __shared__ float red[256];
    red[threadIdx.x] = m;
    __syncthreads();
    for (int s = 128; s > 0; s >>= 1) {
        if (threadIdx.x < s) red[threadIdx.x] = fmaxf(red[threadIdx.x], red[threadIdx.x + s]);
        __syncthreads();
    }
    if (threadIdx.x == 0) g_pool[(b * HC + cc) * 4 + q] = red[0];
}

// ---------------------------------------------------------------------------
// Kernel 2: tiny 2x2 dwconvs + base[b][q][o]
// ---------------------------------------------------------------------------
__global__ __launch_bounds__(512) void base_kernel(
    const float* __restrict__ w2, const float* __restrict__ b2,
    const float* __restrict__ w3, const float* __restrict__ b3,
    const float* __restrict__ w4, const float* __restrict__ b4,
    const float* __restrict__ wa, const float* __restrict__ ba)
{
    int b  = blockIdx.x >> 2;
    int oc = (blockIdx.x & 3) * 128;
    __shared__ float catlow[256][4];
    int t = threadIdx.x;
    if (t < 256) {
        const float* wp;
        float bias;
        if (t < 128)       { wp = w2 + t * 9;         bias = b2[t];        }
        else if (t < 192)  { wp = w3 + (t - 128) * 9; bias = b3[t - 128]; }
        else               { wp = w4 + (t - 192) * 9; bias = b4[t - 192]; }
        float i00 = g_pool[(b * HC + t) * 4 + 0];
        float i01 = g_pool[(b * HC + t) * 4 + 1];
        float i10 = g_pool[(b * HC + t) * 4 + 2];
        float i11 = g_pool[(b * HC + t) * 4 + 3];
        catlow[t][0] = i00*wp[4] + i01*wp[5] + i10*wp[7] + i11*wp[8] + bias;
        catlow[t][1] = i00*wp[3] + i01*wp[4] + i10*wp[6] + i11*wp[7] + bias;
        catlow[t][2] = i00*wp[1] + i01*wp[2] + i10*wp[4] + i11*wp[5] + bias;
        catlow[t][3] = i00*wp[0] + i01*wp[1] + i10*wp[3] + i11*wp[4] + bias;
    }
    __syncthreads();
    int o    = oc + (t >> 2);
    int part = t & 3;
    int cc0  = part * 64;
    float a0 = 0.f, a1 = 0.f, a2 = 0.f, a3 = 0.f;
    #pragma unroll 4
    for (int cc = cc0; cc < cc0 + 64; ++cc) {
        float wv = wa[o * CFULL + 256 + cc];
        a0 = fmaf(wv, catlow[cc][0], a0);
        a1 = fmaf(wv, catlow[cc][1], a1);
        a2 = fmaf(wv, catlow[cc][2], a2);
        a3 = fmaf(wv, catlow[cc][3], a3);
    }
    #pragma unroll
    for (int off = 1; off < 4; off <<= 1) {
        a0 += __shfl_xor_sync(0xffffffff, a0, off);
        a1 += __shfl_xor_sync(0xffffffff, a1, off);
        a2 += __shfl_xor_sync(0xffffffff, a2, off);
        a3 += __shfl_xor_sync(0xffffffff, a3, off);
    }
    if (part == 0) {
        float bav = ba[o];
        g_base[(b * 4 + 0) * CFULL + o] = a0 + bav;
        g_base[(b * 4 + 1) * CFULL + o] = a1 + bav;
        g_base[(b * 4 + 2) * CFULL + o] = a2 + bav;
        g_base[(b * 4 + 3) * CFULL + o] = a3 + bav;
    }
}

// ---------------------------------------------------------------------------
// Kernel 3: dwconv3x3 on channels 0..255 -> g_x1 [b][k][n] (R3 version).
// block = (b, c, half of 64 rows). smem tile 66x136, data at cols [4..131].
// ---------------------------------------------------------------------------
__global__ __launch_bounds__(256) void dwconv_kernel(
    const float* __restrict__ x, const float* __restrict__ w1, const float* __restrict__ b1)
{
    int blk  = blockIdx.x;
    int half = blk & 1;
    int c    = (blk >> 1) & 255;
    int b    = blk >> 9;
    int r0   = half * 64;

    __shared__ float tile[66][136];
    const float* xin = x + ((size_t)(b * CFULL + c)) * HW;
    const float4* xin4 = reinterpret_cast<const float4*>(xin);

    for (int i = threadIdx.x; i < 66 * 32; i += 256) {
        int r = i >> 5, c4 = i & 31;
        int gr = r0 + r - 1;
        float4 v = make_float4(0.f, 0.f, 0.f, 0.f);
        if (gr >= 0 && gr < HH) v = xin4[gr * 32 + c4];
        *reinterpret_cast<float4*>(&tile[r][4 + c4 * 4]) = v;
    }
    if (threadIdx.x < 66) {
        tile[threadIdx.x][3]   = 0.f;
        tile[threadIdx.x][132] = 0.f;
    }
    __syncthreads();

    const float* wp = w1 + c * 9;
    float w00 = wp[0], w01 = wp[1], w02 = wp[2];
    float w10 = wp[3], w11 = wp[4], w12 = wp[5];
    float w20 = wp[6], w21 = wp[7], w22 = wp[8];
    float bias = b1[c];

    int r  = threadIdx.x >> 2;          // output row 0..63 within half
    int cb = (threadIdx.x & 3) * 32;    // 32 output cols

    float* outp = g_x1 + ((size_t)(b * HC + c)) * HW + (r0 + r) * WW;

    #pragma unroll
    for (int g = 0; g < 8; ++g) {
        int c0 = cb + g * 4;
        float4 o = make_float4(bias, bias, bias, bias);
        #pragma unroll
        for (int rr = 0; rr < 3; ++rr) {
            float wl = (rr == 0) ? w00 : (rr == 1) ? w10 : w20;
            float wc = (rr == 0) ? w01 : (rr == 1) ? w11 : w21;
            float wr = (rr == 0) ? w02 : (rr == 1) ? w12 : w22;
            const float* row = &tile[r + rr][0];
            float4 m = *reinterpret_cast<const float4*>(&row[c0 + 4]);
            float lv = row[c0 + 3];
            float rv = row[c0 + 8];
            o.x = fmaf(wl, lv,  fmaf(wc, m.x, fmaf(wr, m.y, o.x)));
            o.y = fmaf(wl, m.x, fmaf(wc, m.y, fmaf(wr, m.z, o.y)));
            o.z = fmaf(wl, m.y, fmaf(wc, m.z, fmaf(wr, m.w, o.z)));
            o.w = fmaf(wl, m.z, fmaf(wc, m.w, fmaf(wr, rv,  o.w)));
        }
        *reinterpret_cast<float4*>(&outp[c0]) = o;
    }
}

// ---------------------------------------------------------------------------
// Kernel 4: tf32 GEMM — ldmatrix A + scalar-LDS B, cp.async double buffer,
// single sync/iter, m-block-fastest grid for B-tile L2 reuse.
// ---------------------------------------------------------------------------
__device__ __forceinline__ float gelu_exact(float v) {
    return 0.5f * v * (1.0f + erff(v * 0.70710678118654752f));
}
__device__ __forceinline__ void mma_tf32(float (&d)[4], const uint32_t (&a)[4],
                                         uint32_t b0, uint32_t b1) {
    asm volatile(
        "mma.sync.aligned.m16n8k8.row.col.f32.tf32.tf32.f32 "
        "{%0,%1,%2,%3}, {%4,%5,%6,%7}, {%8,%9}, {%0,%1,%2,%3};"
        : "+f"(d[0]), "+f"(d[1]), "+f"(d[2]), "+f"(d[3])
        : "r"(a[0]), "r"(a[1]), "r"(a[2]), "r"(a[3]), "r"(b0), "r"(b1));
}
__device__ __forceinline__ void cp_async16(uint32_t dst, const void* src) {
    asm volatile("cp.async.cg.shared.global [%0], [%1], 16;" :: "r"(dst), "l"(src));
}
__device__ __forceinline__ void ldsm4(uint32_t (&r)[4], uint32_t addr) {
    asm volatile("ldmatrix.sync.aligned.m8n8.x4.shared.b16 {%0,%1,%2,%3}, [%4];"
                 : "=r"(r[0]), "=r"(r[1]), "=r"(r[2]), "=r"(r[3]) : "r"(addr));
}

#define BM 128
#define BN 128
#define BK 32
#define AS_STRIDE 36
#define BS_STRIDE 136
#define AS_ELEMS (BM * AS_STRIDE)   // 4608
#define BS_ELEMS (BK * BS_STRIDE)   // 4352
#define GEMM_SMEM_BYTES ((2 * AS_ELEMS + 2 * BS_ELEMS) * 4)  // 71680

__global__ __launch_bounds__(256, 2) void gemm_gelu_kernel(
    const float* __restrict__ x, const float* __restrict__ wa, float* __restrict__ out)
{
    extern __shared__ uint32_t smem[];
    uint32_t* As0 = smem;                      // [2][BM][AS_STRIDE]
    uint32_t* Bs0 = smem + 2 * AS_ELEMS;       // [2][BK][BS_STRIDE]

    int m0 = blockIdx.x * BM;       // m-block FASTEST: 4 CTAs share one B tile
    int bx = blockIdx.y;            // image row; n0 = bx*128
    int b  = blockIdx.z;
    int tid = threadIdx.x;
    int lane = tid & 31, warp = tid >> 5;
    int warpM = warp & 3;
    int warpN = warp >> 2;

    const float* x1b = g_x1 + (size_t)b * HC * HW;
    int n0 = bx * BN;

    // cp.async indices
    int a_row[4], a_kc[4], b_row[4], b_nc[4];
    #pragma unroll
    for (int j = 0; j < 4; ++j) {
        int idx = tid + 256 * j;
        a_row[j] = idx >> 3;  a_kc[j] = (idx & 7) * 4;    // 128 rows x 8 chunks
        b_row[j] = idx >> 5;  b_nc[j] = (idx & 31) * 4;   // 32 rows x 32 chunks
    }

    uint32_t as_base = (uint32_t)__cvta_generic_to_shared(As0);
    uint32_t bs_base = (uint32_t)__cvta_generic_to_shared(Bs0);

    auto load_stage = [&](int k0, int s) {
        #pragma unroll
        for (int j = 0; j < 4; ++j) {
            const float* src = wa + (size_t)(m0 + a_row[j]) * CFULL + k0 + a_kc[j];
            uint32_t dst = as_base + (s * AS_ELEMS + a_row[j] * AS_STRIDE + a_kc[j]) * 4;
            cp_async16(dst, src);
        }
        #pragma unroll
        for (int j = 0; j < 4; ++j) {
            const float* src = x1b + (size_t)(k0 + b_row[j]) * HW + n0 + b_nc[j];
            uint32_t dst = bs_base + (s * BS_ELEMS + b_row[j] * BS_STRIDE + b_nc[j]) * 4;
            cp_async16(dst, src);
        }
        asm volatile("cp.async.commit_group;" ::: "memory");
    };

    // ldmatrix per-lane offsets for A
    int j4 = lane >> 3;
    int a_r = ((j4 & 1) * 8) + (lane & 7);
    int a_c = (j4 >> 1) * 4;
    int aoff0 = (warpM * 32 +  0 + a_r) * AS_STRIDE + a_c;
    int aoff1 = (warpM * 32 + 16 + a_r) * AS_STRIDE + a_c;

    float acc[2][8][4] = {};

    load_stage(0, 0);

    #pragma unroll 1
    for (int it = 0; it < HC / BK; ++it) {
        asm volatile("cp.async.wait_group 0;" ::: "memory");
        __syncthreads();
        if (it < HC / BK - 1) load_stage((it + 1) * BK, (it + 1) & 1);

        int s = it & 1;
        uint32_t aB = as_base + s * AS_ELEMS * 4;
        const uint32_t* Bs = Bs0 + s * BS_ELEMS;

        #pragma unroll
        for (int ks = 0; ks < 4; ++ks) {
            int k = ks * 8;
            uint32_t af[2][4];
            ldsm4(af[0], aB + (aoff0 + k) * 4);
            ldsm4(af[1], aB + (aoff1 + k) * 4);
            #pragma unroll
            for (int nt = 0; nt < 8; ++nt) {
                int n = warpN * 64 + nt * 8 + (lane >> 2);
                const uint32_t* Bc = Bs + (k + (lane & 3)) * BS_STRIDE + n;
                uint32_t bf0 = Bc[0];
                uint32_t bf1 = Bc[4 * BS_STRIDE];
                mma_tf32(acc[0][nt], af[0], bf0, bf1);
                mma_tf32(acc[1][nt], af[1], bf0, bf1);
            }
        }
    }

    // Epilogue: +base, exact GELU, gate by x, store.
    int q = ((bx >= 64) ? 2 : 0) + warpN;
    const float* basep = g_base + (b * 4 + q) * CFULL;

    #pragma unroll
    for (int mt = 0; mt < 2; ++mt) {
        int mrow0 = m0 + warpM * 32 + mt * 16 + (lane >> 2);
        int mrow1 = mrow0 + 8;
        float bs0 = basep[mrow0];
        float bs1 = basep[mrow1];
        #pragma unroll
        for (int nt = 0; nt < 8; ++nt) {
            int n = n0 + warpN * 64 + nt * 8 + (lane & 3) * 2;
            size_t off0 = ((size_t)(b * CFULL + mrow0)) * HW + n;
            size_t off1 = ((size_t)(b * CFULL + mrow1)) * HW + n;
            float2 xv0 = *reinterpret_cast<const float2*>(x + off0);
            float2 xv1 = *reinterpret_cast<const float2*>(x + off1);
            float2 r0, r1;
            r0.x = gelu_exact(acc[mt][nt][0] + bs0) * xv0.x;
            r0.y = gelu_exact(acc[mt][nt][1] + bs0) * xv0.y;
            r1.x = gelu_exact(acc[mt][nt][2] + bs1) * xv1.x;
            r1.y = gelu_exact(acc[mt][nt][3] + bs1) * xv1.y;
            *reinterpret_cast<float2*>(out + off0) = r0;
            *reinterpret_cast<float2*>(out + off1) = r1;
        }
    }
}

// ---------------------------------------------------------------------------
extern "C" void kernel_launch(void* const* d_in, const int* in_sizes, int n_in,
                              void* d_out, int out_size) {
    const float* x  = (const float*)d_in[0];
    const float* w1 = (const float*)d_in[1];
    const float* b1 = (const float*)d_in[2];
    const float* w2 = (const float*)d_in[3];
    const float* b2 = (const float*)d_in[4];
    const float* w3 = (const float*)d_in[5];
    const float* b3 = (const float*)d_in[6];
    const float* w4 = (const float*)d_in[7];
    const float* b4 = (const float*)d_in[8];
    const float* wa = (const float*)d_in[9];
    const float* ba = (const float*)d_in[10];
    float* out = (float*)d_out;

    cudaFuncSetAttribute(gemm_gelu_kernel,
                         cudaFuncAttributeMaxDynamicSharedMemorySize, GEMM_SMEM_BYTES);

    pool_kernel<<<BATCH * HC * 4, 256>>>(x);
    base_kernel<<<16, 512>>>(w2, b2, w3, b3, w4, b4, wa, ba);
    dwconv_kernel<<<BATCH * HC * 2, 256>>>(x, w1, b1);
    gemm_gelu_kernel<<<dim3(CFULL / BM, HH, BATCH), 256, GEMM_SMEM_BYTES>>>(x, wa, out);
}

// round 8
// speedup vs baseline: 1.7937x; 1.0014x over previous
#include <cuda_runtime.h>
#include <math.h>
#include <stdint.h>

#define BATCH 4
#define CFULL 512
#define HC 256
#define HH 128
#define WW 128
#define HW (HH*WW)

// x1 transposed: [b][p(pixel)][k(channel)], k contiguous
__device__ float g_x1t[BATCH * HW * HC];
__device__ float g_pool[BATCH * HC * 4];
__device__ float g_base[BATCH * 4 * CFULL];

// ---------------------------------------------------------------------------
// Kernel 1: adaptive max pool of channels 256..511 to 2x2
// ---------------------------------------------------------------------------
__global__ __launch_bounds__(256) void pool_kernel(const float* __restrict__ x) {
    int blk = blockIdx.x;
    int q  = blk & 3;
    int cc = (blk >> 2) & 255;
    int b  = blk >> 10;
    int qh = q >> 1, qw = q & 1;
    const float* xin = x + ((size_t)(b * CFULL + 256 + cc)) * HW + qh * 64 * WW + qw * 64;
    const float4* xin4 = reinterpret_cast<const float4*>(xin);

    float m = -INFINITY;
    for (int i = threadIdx.x; i < 1024; i += 256) {
        int r = i >> 4, c4 = i & 15;
        float4 v = xin4[r * 32 + c4];
        m = fmaxf(m, fmaxf(fmaxf(v.x, v.y), fmaxf(v.z, v.w)));
    }
    __shared__ float red[256];
    red[threadIdx.x] = m;
    __syncthreads();
    for (int s = 128; s > 0; s >>= 1) {
        if (threadIdx.x < s) red[threadIdx.x] = fmaxf(red[threadIdx.x], red[threadIdx.x + s]);
        __syncthreads();
    }
    if (threadIdx.x == 0) g_pool[(b * HC + cc) * 4 + q] = red[0];
}

// ---------------------------------------------------------------------------
// Kernel 2: tiny 2x2 dwconvs + base[b][q][o]
// ---------------------------------------------------------------------------
__global__ __launch_bounds__(512) void base_kernel(
    const float* __restrict__ w2, const float* __restrict__ b2,
    const float* __restrict__ w3, const float* __restrict__ b3,
    const float* __restrict__ w4, const float* __restrict__ b4,
    const float* __restrict__ wa, const float* __restrict__ ba)
{
    int b  = blockIdx.x >> 2;
    int oc = (blockIdx.x & 3) * 128;
    __shared__ float catlow[256][4];
    int t = threadIdx.x;
    if (t < 256) {
        const float* wp;
        float bias;
        if (t < 128)       { wp = w2 + t * 9;         bias = b2[t];        }
        else if (t < 192)  { wp = w3 + (t - 128) * 9; bias = b3[t - 128]; }
        else               { wp = w4 + (t - 192) * 9; bias = b4[t - 192]; }
        float i00 = g_pool[(b * HC + t) * 4 + 0];
        float i01 = g_pool[(b * HC + t) * 4 + 1];
        float i10 = g_pool[(b * HC + t) * 4 + 2];
        float i11 = g_pool[(b * HC + t) * 4 + 3];
        catlow[t][0] = i00*wp[4] + i01*wp[5] + i10*wp[7] + i11*wp[8] + bias;
        catlow[t][1] = i00*wp[3] + i01*wp[4] + i10*wp[6] + i11*wp[7] + bias;
        catlow[t][2] = i00*wp[1] + i01*wp[2] + i10*wp[4] + i11*wp[5] + bias;
        catlow[t][3] = i00*wp[0] + i01*wp[1] + i10*wp[3] + i11*wp[4] + bias;
    }
    __syncthreads();
    int o    = oc + (t >> 2);
    int part = t & 3;
    int cc0  = part * 64;
    float a0 = 0.f, a1 = 0.f, a2 = 0.f, a3 = 0.f;
    #pragma unroll 4
    for (int cc = cc0; cc < cc0 + 64; ++cc) {
        float wv = wa[o * CFULL + 256 + cc];
        a0 = fmaf(wv, catlow[cc][0], a0);
        a1 = fmaf(wv, catlow[cc][1], a1);
        a2 = fmaf(wv, catlow[cc][2], a2);
        a3 = fmaf(wv, catlow[cc][3], a3);
    }
    #pragma unroll
    for (int off = 1; off < 4; off <<= 1) {
        a0 += __shfl_xor_sync(0xffffffff, a0, off);
        a1 += __shfl_xor_sync(0xffffffff, a1, off);
        a2 += __shfl_xor_sync(0xffffffff, a2, off);
        a3 += __shfl_xor_sync(0xffffffff, a3, off);
    }
    if (part == 0) {
        float bav = ba[o];
        g_base[(b * 4 + 0) * CFULL + o] = a0 + bav;
        g_base[(b * 4 + 1) * CFULL + o] = a1 + bav;
        g_base[(b * 4 + 2) * CFULL + o] = a2 + bav;
        g_base[(b * 4 + 3) * CFULL + o] = a3 + bav;
    }
}

// ---------------------------------------------------------------------------
// Kernel 3: dwconv3x3 + transpose -> g_x1t[b][p][k].
// block = (b, image row). 8 channel-chunks of 32; input staged via smem
// (coalesced), output stores are k-contiguous 128B per warp (coalesced).
// ---------------------------------------------------------------------------
#define STW 137
#define DW_SMEM_BYTES (32 * 3 * STW * 4)   // 52,608

__global__ __launch_bounds__(256) void dwconvT_kernel(
    const float* __restrict__ x, const float* __restrict__ w1, const float* __restrict__ b1)
{
    extern __shared__ float stage[];   // [32 ch][3 rr][STW]
    int row = blockIdx.x & 127;
    int b   = blockIdx.x >> 7;
    int tid = threadIdx.x;
    int kl = tid & 31;
    int ng = tid >> 5;
    int c0 = ng * 16;

    if (tid < 96) {
        int ch = tid / 3, rr = tid - 3 * ch;
        stage[ch * (3 * STW) + rr * STW + 3]   = 0.f;
        stage[ch * (3 * STW) + rr * STW + 132] = 0.f;
    }

    float* outbase = g_x1t + ((size_t)b * HW + (size_t)row * WW) * HC;

    for (int cc = 0; cc < 8; ++cc) {
        __syncthreads();
        #pragma unroll
        for (int j = 0; j < 12; ++j) {
            int i = tid + 256 * j;          // [0, 3072)
            int c4 = i & 31;
            int g3 = i >> 5;                // [0, 96)
            int ch = g3 / 3;
            int rr = g3 - 3 * ch;
            int gr = row + rr - 1;
            float4 v = make_float4(0.f, 0.f, 0.f, 0.f);
            if (gr >= 0 && gr < HH)
                v = *reinterpret_cast<const float4*>(
                    x + ((size_t)(b * CFULL + cc * 32 + ch)) * HW + gr * WW + c4 * 4);
            float* sp = stage + ch * (3 * STW) + rr * STW + 4 + c4 * 4;
            sp[0] = v.x; sp[1] = v.y; sp[2] = v.z; sp[3] = v.w;
        }
        __syncthreads();
        int k = cc * 32 + kl;
        const float* wp = w1 + k * 9;
        float w00 = wp[0], w01 = wp[1], w02 = wp[2];
        float w10 = wp[3], w11 = wp[4], w12 = wp[5];
        float w20 = wp[6], w21 = wp[7], w22 = wp[8];
        float bias = b1[k];

        float rv[3][18];
        const float* sb = stage + kl * (3 * STW);
        #pragma unroll
        for (int rr = 0; rr < 3; ++rr) {
            #pragma unroll
            for (int i = 0; i < 18; ++i)
                rv[rr][i] = sb[rr * STW + 3 + c0 + i];
        }
        #pragma unroll
        for (int c = 0; c < 16; ++c) {
            float acc = bias;
            acc = fmaf(w00, rv[0][c],     acc);
            acc = fmaf(w01, rv[0][c + 1], acc);
            acc = fmaf(w02, rv[0][c + 2], acc);
            acc = fmaf(w10, rv[1][c],     acc);
            acc = fmaf(w11, rv[1][c + 1], acc);
            acc = fmaf(w12, rv[1][c + 2], acc);
            acc = fmaf(w20, rv[2][c],     acc);
            acc = fmaf(w21, rv[2][c + 1], acc);
            acc = fmaf(w22, rv[2][c + 2], acc);
            outbase[(size_t)(c0 + c) * HC + k] = acc;   // 128B warp store
        }
    }
}

// ---------------------------------------------------------------------------
// Kernel 4: tf32 GEMM, full ldmatrix (A and B), cp.async double buffer,
// single sync/iter, m-fastest grid for B-tile L2 reuse.
// A = wa[m][k] K-major; B = g_x1t[n][k] K-major. D = A * B^T.
// ---------------------------------------------------------------------------
__device__ __forceinline__ float gelu_exact(float v) {
    return 0.5f * v * (1.0f + erff(v * 0.70710678118654752f));
}
__device__ __forceinline__ void mma_tf32(float (&d)[4], const uint32_t (&a)[4],
                                         uint32_t b0, uint32_t b1) {
    asm volatile(
        "mma.sync.aligned.m16n8k8.row.col.f32.tf32.tf32.f32 "
        "{%0,%1,%2,%3}, {%4,%5,%6,%7}, {%8,%9}, {%0,%1,%2,%3};"
        : "+f"(d[0]), "+f"(d[1]), "+f"(d[2]), "+f"(d[3])
        : "r"(a[0]), "r"(a[1]), "r"(a[2]), "r"(a[3]), "r"(b0), "r"(b1));
}
__device__ __forceinline__ void cp_async16(uint32_t dst, const void* src) {
    asm volatile("cp.async.cg.shared.global [%0], [%1], 16;" :: "r"(dst), "l"(src));
}
__device__ __forceinline__ void ldsm4(uint32_t (&r)[4], uint32_t addr) {
    asm volatile("ldmatrix.sync.aligned.m8n8.x4.shared.b16 {%0,%1,%2,%3}, [%4];"
                 : "=r"(r[0]), "=r"(r[1]), "=r"(r[2]), "=r"(r[3]) : "r"(addr));
}

#define BM 128
#define BN 128
#define BK 32
#define TSTRIDE 36
#define T_ELEMS (128 * TSTRIDE)            // 4608 per tile per stage
#define GEMM_SMEM_BYTES (4 * T_ELEMS * 4)  // 73728

__global__ __launch_bounds__(256, 2) void gemm_gelu_kernel(
    const float* __restrict__ x, const float* __restrict__ wa, float* __restrict__ out)
{
    extern __shared__ uint32_t smem[];
    uint32_t* As0 = smem;                  // [2][128 m][36]
    uint32_t* Bs0 = smem + 2 * T_ELEMS;    // [2][128 n][36]

    int m0 = blockIdx.x * BM;              // m-block FASTEST: B-tile L2 reuse
    int bx = blockIdx.y;                   // image row; n0 = bx*128
    int b  = blockIdx.z;
    int tid = threadIdx.x;
    int lane = tid & 31, warp = tid >> 5;
    int warpM = warp & 3;
    int warpN = warp >> 2;

    const float* x1b = g_x1t + ((size_t)b * HW + (size_t)bx * WW) * HC;  // [n][256]
    int n0 = bx * BN;

    // cp.async indices: 128 rows x 8 chunks of 16B = 1024, 4 per thread
    int rowi[4], kci[4];
    #pragma unroll
    for (int j = 0; j < 4; ++j) {
        int idx = tid + 256 * j;
        rowi[j] = idx >> 3;
        kci[j]  = (idx & 7) * 4;
    }

    uint32_t as_base = (uint32_t)__cvta_generic_to_shared(As0);
    uint32_t bs_base = (uint32_t)__cvta_generic_to_shared(Bs0);

    auto load_stage = [&](int k0, int s) {
        #pragma unroll
        for (int j = 0; j < 4; ++j) {
            const float* src = wa + (size_t)(m0 + rowi[j]) * CFULL + k0 + kci[j];
            uint32_t dst = as_base + (s * T_ELEMS + rowi[j] * TSTRIDE + kci[j]) * 4;
            cp_async16(dst, src);
        }
        #pragma unroll
        for (int j = 0; j < 4; ++j) {
            const float* src = x1b + (size_t)rowi[j] * HC + k0 + kci[j];
            uint32_t dst = bs_base + (s * T_ELEMS + rowi[j] * TSTRIDE + kci[j]) * 4;
            cp_async16(dst, src);
        }
        asm volatile("cp.async.commit_group;" ::: "memory");
    };

    // ldmatrix per-lane offsets (in elements)
    int j4 = lane >> 3;
    int a_row = ((j4 & 1) * 8) + (lane & 7);
    int a_col = (j4 >> 1) * 4;
    int b_row = ((j4 >> 1) * 8) + (lane & 7);
    int b_col = (j4 & 1) * 4;
    int aoff0 = (warpM * 32 +  0 + a_row) * TSTRIDE + a_col;
    int aoff1 = (warpM * 32 + 16 + a_row) * TSTRIDE + a_col;
    int boff[4];
    #pragma unroll
    for (int ntp = 0; ntp < 4; ++ntp)
        boff[ntp] = (warpN * 64 + ntp * 16 + b_row) * TSTRIDE + b_col;

    float acc[2][8][4] = {};

    load_stage(0, 0);

    #pragma unroll 1
    for (int it = 0; it < HC / BK; ++it) {
        asm volatile("cp.async.wait_group 0;" ::: "memory");
        __syncthreads();
        if (it < HC / BK - 1) load_stage((it + 1) * BK, (it + 1) & 1);

        int s = it & 1;
        uint32_t aB = as_base + s * T_ELEMS * 4;
        uint32_t bB = bs_base + s * T_ELEMS * 4;

        #pragma unroll
        for (int ks = 0; ks < 4; ++ks) {
            uint32_t af[2][4];
            ldsm4(af[0], aB + (aoff0 + ks * 8) * 4);
            ldsm4(af[1], aB + (aoff1 + ks * 8) * 4);
            #pragma unroll
            for (int ntp = 0; ntp < 4; ++ntp) {
                uint32_t bb[4];
                ldsm4(bb, bB + (boff[ntp] + ks * 8) * 4);
                mma_tf32(acc[0][2 * ntp    ], af[0], bb[0], bb[1]);
                mma_tf32(acc[1][2 * ntp    ], af[1], bb[0], bb[1]);
                mma_tf32(acc[0][2 * ntp + 1], af[0], bb[2], bb[3]);
                mma_tf32(acc[1][2 * ntp + 1], af[1], bb[2], bb[3]);
            }
        }
    }

    // Epilogue: +base, exact GELU, gate by x, store.
    int q = ((bx >= 64) ? 2 : 0) + warpN;
    const float* basep = g_base + (b * 4 + q) * CFULL;

    #pragma unroll
    for (int mt = 0; mt < 2; ++mt) {
        int mrow0 = m0 + warpM * 32 + mt * 16 + (lane >> 2);
        int mrow1 = mrow0 + 8;
        float bs0 = basep[mrow0];
        float bs1 = basep[mrow1];
        #pragma unroll
        for (int nt = 0; nt < 8; ++nt) {
            int n = n0 + warpN * 64 + nt * 8 + (lane & 3) * 2;
            size_t off0 = ((size_t)(b * CFULL + mrow0)) * HW + n;
            size_t off1 = ((size_t)(b * CFULL + mrow1)) * HW + n;
            float2 xv0 = *reinterpret_cast<const float2*>(x + off0);
            float2 xv1 = *reinterpret_cast<const float2*>(x + off1);
            float2 r0, r1;
            r0.x = gelu_exact(acc[mt][nt][0] + bs0) * xv0.x;
            r0.y = gelu_exact(acc[mt][nt][1] + bs0) * xv0.y;
            r1.x = gelu_exact(acc[mt][nt][2] + bs1) * xv1.x;
            r1.y = gelu_exact(acc[mt][nt][3] + bs1) * xv1.y;
            *reinterpret_cast<float2*>(out + off0) = r0;
            *reinterpret_cast<float2*>(out + off1) = r1;
        }
    }
}

// ---------------------------------------------------------------------------
extern "C" void kernel_launch(void* const* d_in, const int* in_sizes, int n_in,
                              void* d_out, int out_size) {
    const float* x  = (const float*)d_in[0];
    const float* w1 = (const float*)d_in[1];
    const float* b1 = (const float*)d_in[2];
    const float* w2 = (const float*)d_in[3];
    const float* b2 = (const float*)d_in[4];
    const float* w3 = (const float*)d_in[5];
    const float* b3 = (const float*)d_in[6];
    const float* w4 = (const float*)d_in[7];
    const float* b4 = (const float*)d_in[8];
    const float* wa = (const float*)d_in[9];
    const float* ba = (const float*)d_in[10];
    float* out = (float*)d_out;

    cudaFuncSetAttribute(dwconvT_kernel,
                         cudaFuncAttributeMaxDynamicSharedMemorySize, DW_SMEM_BYTES);
    cudaFuncSetAttribute(gemm_gelu_kernel,
                         cudaFuncAttributeMaxDynamicSharedMemorySize, GEMM_SMEM_BYTES);

    pool_kernel<<<BATCH * HC * 4, 256>>>(x);
    base_kernel<<<16, 512>>>(w2, b2, w3, b3, w4, b4, wa, ba);
    dwconvT_kernel<<<BATCH * HH, 256, DW_SMEM_BYTES>>>(x, w1, b1);
    gemm_gelu_kernel<<<dim3(CFULL / BM, HH, BATCH), 256, GEMM_SMEM_BYTES>>>(x, wa, out);
}

// round 9
// speedup vs baseline: 1.8191x; 1.0142x over previous
#include <cuda_runtime.h>
#include <math.h>
#include <stdint.h>

#define BATCH 4
#define CFULL 512
#define HC 256
#define HH 128
#define WW 128
#define HW (HH*WW)

// x1 transposed: [b][p(pixel)][k(channel)], k contiguous
__device__ float g_x1t[BATCH * HW * HC];
__device__ float g_pool[BATCH * HC * 4];
__device__ float g_base[BATCH * 4 * CFULL];

// ---------------------------------------------------------------------------
// Kernel 1: adaptive max pool of channels 256..511 to 2x2
// ---------------------------------------------------------------------------
__global__ __launch_bounds__(256) void pool_kernel(const float* __restrict__ x) {
    int blk = blockIdx.x;
    int q  = blk & 3;
    int cc = (blk >> 2) & 255;
    int b  = blk >> 10;
    int qh = q >> 1, qw = q & 1;
    const float* xin = x + ((size_t)(b * CFULL + 256 + cc)) * HW + qh * 64 * WW + qw * 64;
    const float4* xin4 = reinterpret_cast<const float4*>(xin);

    float m = -INFINITY;
    for (int i = threadIdx.x; i < 1024; i += 256) {
        int r = i >> 4, c4 = i & 15;
        float4 v = xin4[r * 32 + c4];
        m = fmaxf(m, fmaxf(fmaxf(v.x, v.y), fmaxf(v.z, v.w)));
    }
    __shared__ float red[256];
    red[threadIdx.x] = m;
    __syncthreads();
    for (int s = 128; s > 0; s >>= 1) {
        if (threadIdx.x < s) red[threadIdx.x] = fmaxf(red[threadIdx.x], red[threadIdx.x + s]);
        __syncthreads();
    }
    if (threadIdx.x == 0) g_pool[(b * HC + cc) * 4 + q] = red[0];
}

// ---------------------------------------------------------------------------
// Kernel 2: tiny 2x2 dwconvs + base[b][q][o]
// ---------------------------------------------------------------------------
__global__ __launch_bounds__(512) void base_kernel(
    const float* __restrict__ w2, const float* __restrict__ b2,
    const float* __restrict__ w3, const float* __restrict__ b3,
    const float* __restrict__ w4, const float* __restrict__ b4,
    const float* __restrict__ wa, const float* __restrict__ ba)
{
    int b  = blockIdx.x >> 2;
    int oc = (blockIdx.x & 3) * 128;
    __shared__ float catlow[256][4];
    int t = threadIdx.x;
    if (t < 256) {
        const float* wp;
        float bias;
        if (t < 128)       { wp = w2 + t * 9;         bias = b2[t];        }
        else if (t < 192)  { wp = w3 + (t - 128) * 9; bias = b3[t - 128]; }
        else               { wp = w4 + (t - 192) * 9; bias = b4[t - 192]; }
        float i00 = g_pool[(b * HC + t) * 4 + 0];
        float i01 = g_pool[(b * HC + t) * 4 + 1];
        float i10 = g_pool[(b * HC + t) * 4 + 2];
        float i11 = g_pool[(b * HC + t) * 4 + 3];
        catlow[t][0] = i00*wp[4] + i01*wp[5] + i10*wp[7] + i11*wp[8] + bias;
        catlow[t][1] = i00*wp[3] + i01*wp[4] + i10*wp[6] + i11*wp[7] + bias;
        catlow[t][2] = i00*wp[1] + i01*wp[2] + i10*wp[4] + i11*wp[5] + bias;
        catlow[t][3] = i00*wp[0] + i01*wp[1] + i10*wp[3] + i11*wp[4] + bias;
    }
    __syncthreads();
    int o    = oc + (t >> 2);
    int part = t & 3;
    int cc0  = part * 64;
    float a0 = 0.f, a1 = 0.f, a2 = 0.f, a3 = 0.f;
    #pragma unroll 4
    for (int cc = cc0; cc < cc0 + 64; ++cc) {
        float wv = wa[o * CFULL + 256 + cc];
        a0 = fmaf(wv, catlow[cc][0], a0);
        a1 = fmaf(wv, catlow[cc][1], a1);
        a2 = fmaf(wv, catlow[cc][2], a2);
        a3 = fmaf(wv, catlow[cc][3], a3);
    }
    #pragma unroll
    for (int off = 1; off < 4; off <<= 1) {
        a0 += __shfl_xor_sync(0xffffffff, a0, off);
        a1 += __shfl_xor_sync(0xffffffff, a1, off);
        a2 += __shfl_xor_sync(0xffffffff, a2, off);
        a3 += __shfl_xor_sync(0xffffffff, a3, off);
    }
    if (part == 0) {
        float bav = ba[o];
        g_base[(b * 4 + 0) * CFULL + o] = a0 + bav;
        g_base[(b * 4 + 1) * CFULL + o] = a1 + bav;
        g_base[(b * 4 + 2) * CFULL + o] = a2 + bav;
        g_base[(b * 4 + 3) * CFULL + o] = a3 + bav;
    }
}

// ---------------------------------------------------------------------------
// Kernel 3: dwconv3x3 + transpose -> g_x1t[b][p][k].
// ---------------------------------------------------------------------------
#define STW 137
#define DW_SMEM_BYTES (32 * 3 * STW * 4)   // 52,608

__global__ __launch_bounds__(256) void dwconvT_kernel(
    const float* __restrict__ x, const float* __restrict__ w1, const float* __restrict__ b1)
{
    extern __shared__ float stage[];   // [32 ch][3 rr][STW]
    int row = blockIdx.x & 127;
    int b   = blockIdx.x >> 7;
    int tid = threadIdx.x;
    int kl = tid & 31;
    int ng = tid >> 5;
    int c0 = ng * 16;

    if (tid < 96) {
        int ch = tid / 3, rr = tid - 3 * ch;
        stage[ch * (3 * STW) + rr * STW + 3]   = 0.f;
        stage[ch * (3 * STW) + rr * STW + 132] = 0.f;
    }

    float* outbase = g_x1t + ((size_t)b * HW + (size_t)row * WW) * HC;

    for (int cc = 0; cc < 8; ++cc) {
        __syncthreads();
        #pragma unroll
        for (int j = 0; j < 12; ++j) {
            int i = tid + 256 * j;
            int c4 = i & 31;
            int g3 = i >> 5;
            int ch = g3 / 3;
            int rr = g3 - 3 * ch;
            int gr = row + rr - 1;
            float4 v = make_float4(0.f, 0.f, 0.f, 0.f);
            if (gr >= 0 && gr < HH)
                v = *reinterpret_cast<const float4*>(
                    x + ((size_t)(b * CFULL + cc * 32 + ch)) * HW + gr * WW + c4 * 4);
            float* sp = stage + ch * (3 * STW) + rr * STW + 4 + c4 * 4;
            sp[0] = v.x; sp[1] = v.y; sp[2] = v.z; sp[3] = v.w;
        }
        __syncthreads();
        int k = cc * 32 + kl;
        const float* wp = w1 + k * 9;
        float w00 = wp[0], w01 = wp[1], w02 = wp[2];
        float w10 = wp[3], w11 = wp[4], w12 = wp[5];
        float w20 = wp[6], w21 = wp[7], w22 = wp[8];
        float bias = b1[k];

        float rv[3][18];
        const float* sb = stage + kl * (3 * STW);
        #pragma unroll
        for (int rr = 0; rr < 3; ++rr) {
            #pragma unroll
            for (int i = 0; i < 18; ++i)
                rv[rr][i] = sb[rr * STW + 3 + c0 + i];
        }
        #pragma unroll
        for (int c = 0; c < 16; ++c) {
            float acc = bias;
            acc = fmaf(w00, rv[0][c],     acc);
            acc = fmaf(w01, rv[0][c + 1], acc);
            acc = fmaf(w02, rv[0][c + 2], acc);
            acc = fmaf(w10, rv[1][c],     acc);
            acc = fmaf(w11, rv[1][c + 1], acc);
            acc = fmaf(w12, rv[1][c + 2], acc);
            acc = fmaf(w20, rv[2][c],     acc);
            acc = fmaf(w21, rv[2][c + 1], acc);
            acc = fmaf(w22, rv[2][c + 2], acc);
            outbase[(size_t)(c0 + c) * HC + k] = acc;
        }
    }
}

// ---------------------------------------------------------------------------
// Kernel 4: tf32 GEMM (full ldmatrix, cp.async) + smem-transposed coalesced
// epilogue (+base, exact GELU, gate by x).
// ---------------------------------------------------------------------------
__device__ __forceinline__ float gelu_exact(float v) {
    return 0.5f * v * (1.0f + erff(v * 0.70710678118654752f));
}
__device__ __forceinline__ void mma_tf32(float (&d)[4], const uint32_t (&a)[4],
                                         uint32_t b0, uint32_t b1) {
    asm volatile(
        "mma.sync.aligned.m16n8k8.row.col.f32.tf32.tf32.f32 "
        "{%0,%1,%2,%3}, {%4,%5,%6,%7}, {%8,%9}, {%0,%1,%2,%3};"
        : "+f"(d[0]), "+f"(d[1]), "+f"(d[2]), "+f"(d[3])
        : "r"(a[0]), "r"(a[1]), "r"(a[2]), "r"(a[3]), "r"(b0), "r"(b1));
}
__device__ __forceinline__ void cp_async16(uint32_t dst, const void* src) {
    asm volatile("cp.async.cg.shared.global [%0], [%1], 16;" :: "r"(dst), "l"(src));
}
__device__ __forceinline__ void ldsm4(uint32_t (&r)[4], uint32_t addr) {
    asm volatile("ldmatrix.sync.aligned.m8n8.x4.shared.b16 {%0,%1,%2,%3}, [%4];"
                 : "=r"(r[0]), "=r"(r[1]), "=r"(r[2]), "=r"(r[3]) : "r"(addr));
}

#define BM 128
#define BN 128
#define BK 32
#define TSTRIDE 36
#define T_ELEMS (128 * TSTRIDE)            // 4608 per tile per stage
#define DPAD 132                           // epilogue tile row stride
#define GEMM_SMEM_BYTES (4 * T_ELEMS * 4)  // 73728 (>= 128*DPAD*4 = 67584)

__global__ __launch_bounds__(256, 2) void gemm_gelu_kernel(
    const float* __restrict__ x, const float* __restrict__ wa, float* __restrict__ out)
{
    extern __shared__ uint32_t smem[];
    uint32_t* As0 = smem;                  // [2][128 m][36]
    uint32_t* Bs0 = smem + 2 * T_ELEMS;    // [2][128 n][36]

    int m0 = blockIdx.x * BM;              // m-block fastest: B-tile L2 reuse
    int bx = blockIdx.y;                   // image row; n0 = bx*128
    int b  = blockIdx.z;
    int tid = threadIdx.x;
    int lane = tid & 31, warp = tid >> 5;
    int warpM = warp & 3;
    int warpN = warp >> 2;

    const float* x1b = g_x1t + ((size_t)b * HW + (size_t)bx * WW) * HC;  // [n][256]

    int rowi[4], kci[4];
    #pragma unroll
    for (int j = 0; j < 4; ++j) {
        int idx = tid + 256 * j;
        rowi[j] = idx >> 3;
        kci[j]  = (idx & 7) * 4;
    }

    uint32_t as_base = (uint32_t)__cvta_generic_to_shared(As0);
    uint32_t bs_base = (uint32_t)__cvta_generic_to_shared(Bs0);

    auto load_stage = [&](int k0, int s) {
        #pragma unroll
        for (int j = 0; j < 4; ++j) {
            const float* src = wa + (size_t)(m0 + rowi[j]) * CFULL + k0 + kci[j];
            uint32_t dst = as_base + (s * T_ELEMS + rowi[j] * TSTRIDE + kci[j]) * 4;
            cp_async16(dst, src);
        }
        #pragma unroll
        for (int j = 0; j < 4; ++j) {
            const float* src = x1b + (size_t)rowi[j] * HC + k0 + kci[j];
            uint32_t dst = bs_base + (s * T_ELEMS + rowi[j] * TSTRIDE + kci[j]) * 4;
            cp_async16(dst, src);
        }
        asm volatile("cp.async.commit_group;" ::: "memory");
    };

    int j4 = lane >> 3;
    int a_row = ((j4 & 1) * 8) + (lane & 7);
    int a_col = (j4 >> 1) * 4;
    int b_row = ((j4 >> 1) * 8) + (lane & 7);
    int b_col = (j4 & 1) * 4;
    int aoff0 = (warpM * 32 +  0 + a_row) * TSTRIDE + a_col;
    int aoff1 = (warpM * 32 + 16 + a_row) * TSTRIDE + a_col;
    int boff[4];
    #pragma unroll
    for (int ntp = 0; ntp < 4; ++ntp)
        boff[ntp] = (warpN * 64 + ntp * 16 + b_row) * TSTRIDE + b_col;

    float acc[2][8][4] = {};

    load_stage(0, 0);

    #pragma unroll 1
    for (int it = 0; it < HC / BK; ++it) {
        asm volatile("cp.async.wait_group 0;" ::: "memory");
        __syncthreads();
        if (it < HC / BK - 1) load_stage((it + 1) * BK, (it + 1) & 1);

        int s = it & 1;
        uint32_t aB = as_base + s * T_ELEMS * 4;
        uint32_t bB = bs_base + s * T_ELEMS * 4;

        #pragma unroll
        for (int ks = 0; ks < 4; ++ks) {
            uint32_t af[2][4];
            ldsm4(af[0], aB + (aoff0 + ks * 8) * 4);
            ldsm4(af[1], aB + (aoff1 + ks * 8) * 4);
            #pragma unroll
            for (int ntp = 0; ntp < 4; ++ntp) {
                uint32_t bb[4];
                ldsm4(bb, bB + (boff[ntp] + ks * 8) * 4);
                mma_tf32(acc[0][2 * ntp    ], af[0], bb[0], bb[1]);
                mma_tf32(acc[1][2 * ntp    ], af[1], bb[0], bb[1]);
                mma_tf32(acc[0][2 * ntp + 1], af[0], bb[2], bb[3]);
                mma_tf32(acc[1][2 * ntp + 1], af[1], bb[2], bb[3]);
            }
        }
    }

    // ===== Epilogue: stage acc tile to smem, then coalesced gelu-gate-store =====
    __syncthreads();   // all warps done reading mainloop smem
    float* Ds = reinterpret_cast<float*>(smem);   // [128 m][DPAD]

    #pragma unroll
    for (int mt = 0; mt < 2; ++mt) {
        int ml = warpM * 32 + mt * 16 + (lane >> 2);
        #pragma unroll
        for (int nt = 0; nt < 8; ++nt) {
            int nl = warpN * 64 + nt * 8 + (lane & 3) * 2;
            *reinterpret_cast<float2*>(&Ds[ml * DPAD + nl]) =
                make_float2(acc[mt][nt][0], acc[mt][nt][1]);
            *reinterpret_cast<float2*>(&Ds[(ml + 8) * DPAD + nl]) =
                make_float2(acc[mt][nt][2], acc[mt][nt][3]);
        }
    }
    __syncthreads();

    int nloc = lane * 4;
    int q = ((bx >= 64) ? 2 : 0) + ((nloc >= 64) ? 1 : 0);
    const float* basep = g_base + (b * 4 + q) * CFULL + m0;
    size_t pixbase = (size_t)bx * WW + nloc;

    #pragma unroll
    for (int i = 0; i < 16; ++i) {
        int m = warp * 16 + i;
        int o = m0 + m;
        float bsv = basep[m];
        float4 d = *reinterpret_cast<const float4*>(&Ds[m * DPAD + nloc]);
        size_t off = ((size_t)(b * CFULL + o)) * HW + pixbase;
        float4 xv = *reinterpret_cast<const float4*>(&x[off]);
        float4 r;
        r.x = gelu_exact(d.x + bsv) * xv.x;
        r.y = gelu_exact(d.y + bsv) * xv.y;
        r.z = gelu_exact(d.z + bsv) * xv.z;
        r.w = gelu_exact(d.w + bsv) * xv.w;
        *reinterpret_cast<float4*>(&out[off]) = r;
    }
}

// ---------------------------------------------------------------------------
extern "C" void kernel_launch(void* const* d_in, const int* in_sizes, int n_in,
                              void* d_out, int out_size) {
    const float* x  = (const float*)d_in[0];
    const float* w1 = (const float*)d_in[1];
    const float* b1 = (const float*)d_in[2];
    const float* w2 = (const float*)d_in[3];
    const float* b2 = (const float*)d_in[4];
    const float* w3 = (const float*)d_in[5];
    const float* b3 = (const float*)d_in[6];
    const float* w4 = (const float*)d_in[7];
    const float* b4 = (const float*)d_in[8];
    const float* wa = (const float*)d_in[9];
    const float* ba = (const float*)d_in[10];
    float* out = (float*)d_out;

    cudaFuncSetAttribute(dwconvT_kernel,
                         cudaFuncAttributeMaxDynamicSharedMemorySize, DW_SMEM_BYTES);
    cudaFuncSetAttribute(gemm_gelu_kernel,
                         cudaFuncAttributeMaxDynamicSharedMemorySize, GEMM_SMEM_BYTES);

    // Fork-join: pool+base on a side stream, dwconvT on the main (captured)
    // stream, join before the gemm. Stream/event creation is not a captured
    // op; events are the documented multi-branch capture pattern.
    cudaStream_t side;
    cudaStreamCreateWithFlags(&side, cudaStreamNonBlocking);
    cudaEvent_t eFork, eJoin;
    cudaEventCreateWithFlags(&eFork, cudaEventDisableTiming);
    cudaEventCreateWithFlags(&eJoin, cudaEventDisableTiming);

    cudaEventRecord(eFork, 0);
    cudaStreamWaitEvent(side, eFork, 0);

    pool_kernel<<<BATCH * HC * 4, 256, 0, side>>>(x);
    base_kernel<<<16, 512, 0, side>>>(w2, b2, w3, b3, w4, b4, wa, ba);
    cudaEventRecord(eJoin, side);

    dwconvT_kernel<<<BATCH * HH, 256, DW_SMEM_BYTES>>>(x, w1, b1);

    cudaStreamWaitEvent(0, eJoin, 0);
    gemm_gelu_kernel<<<dim3(CFULL / BM, HH, BATCH), 256, GEMM_SMEM_BYTES>>>(x, wa, out);
}

// round 10
// speedup vs baseline: 2.2767x; 1.2515x over previous
#include <cuda_runtime.h>
#include <cuda_fp16.h>
#include <math.h>
#include <stdint.h>

#define BATCH 4
#define CFULL 512
#define HC 256
#define HH 128
#define WW 128
#define HW (HH*WW)

// x1 transposed + fp16: [b][p(pixel)][k(channel)], k contiguous
__device__ __align__(16) __half g_x1t[BATCH * HW * HC];
__device__ __align__(16) __half g_wa_h[CFULL * HC];   // wa[:, 0:256] in fp16
__device__ float g_pool[BATCH * HC * 4];
__device__ float g_base[BATCH * 4 * CFULL];

// ---------------------------------------------------------------------------
// Kernel 0: convert wa[:, 0:256] to fp16
// ---------------------------------------------------------------------------
__global__ __launch_bounds__(256) void waconv_kernel(const float* __restrict__ wa) {
    int i = blockIdx.x * 256 + threadIdx.x;     // 512*256 = 131072
    int o = i >> 8, k = i & 255;
    g_wa_h[i] = __float2half_rn(wa[o * CFULL + k]);
}

// ---------------------------------------------------------------------------
// Kernel 1: adaptive max pool of channels 256..511 to 2x2
// ---------------------------------------------------------------------------
__global__ __launch_bounds__(256) void pool_kernel(const float* __restrict__ x) {
    int blk = blockIdx.x;
    int q  = blk & 3;
    int cc = (blk >> 2) & 255;
    int b  = blk >> 10;
    int qh = q >> 1, qw = q & 1;
    const float* xin = x + ((size_t)(b * CFULL + 256 + cc)) * HW + qh * 64 * WW + qw * 64;
    const float4* xin4 = reinterpret_cast<const float4*>(xin);

    float m = -INFINITY;
    for (int i = threadIdx.x; i < 1024; i += 256) {
        int r = i >> 4, c4 = i & 15;
        float4 v = xin4[r * 32 + c4];
        m = fmaxf(m, fmaxf(fmaxf(v.x, v.y), fmaxf(v.z, v.w)));
    }
    __shared__ float red[256];
    red[threadIdx.x] = m;
    __syncthreads();
    for (int s = 128; s > 0; s >>= 1) {
        if (threadIdx.x < s) red[threadIdx.x] = fmaxf(red[threadIdx.x], red[threadIdx.x + s]);
        __syncthreads();
    }
    if (threadIdx.x == 0) g_pool[(b * HC + cc) * 4 + q] = red[0];
}

// ---------------------------------------------------------------------------
// Kernel 2: tiny 2x2 dwconvs + base[b][q][o]
// ---------------------------------------------------------------------------
__global__ __launch_bounds__(512) void base_kernel(
    const float* __restrict__ w2, const float* __restrict__ b2,
    const float* __restrict__ w3, const float* __restrict__ b3,
    const float* __restrict__ w4, const float* __restrict__ b4,
    const float* __restrict__ wa, const float* __restrict__ ba)
{
    int b  = blockIdx.x >> 2;
    int oc = (blockIdx.x & 3) * 128;
    __shared__ float catlow[256][4];
    int t = threadIdx.x;
    if (t < 256) {
        const float* wp;
        float bias;
        if (t < 128)       { wp = w2 + t * 9;         bias = b2[t];        }
        else if (t < 192)  { wp = w3 + (t - 128) * 9; bias = b3[t - 128]; }
        else               { wp = w4 + (t - 192) * 9; bias = b4[t - 192]; }
        float i00 = g_pool[(b * HC + t) * 4 + 0];
        float i01 = g_pool[(b * HC + t) * 4 + 1];
        float i10 = g_pool[(b * HC + t) * 4 + 2];
        float i11 = g_pool[(b * HC + t) * 4 + 3];
        catlow[t][0] = i00*wp[4] + i01*wp[5] + i10*wp[7] + i11*wp[8] + bias;
        catlow[t][1] = i00*wp[3] + i01*wp[4] + i10*wp[6] + i11*wp[7] + bias;
        catlow[t][2] = i00*wp[1] + i01*wp[2] + i10*wp[4] + i11*wp[5] + bias;
        catlow[t][3] = i00*wp[0] + i01*wp[1] + i10*wp[3] + i11*wp[4] + bias;
    }
    __syncthreads();
    int o    = oc + (t >> 2);
    int part = t & 3;
    int cc0  = part * 64;
    float a0 = 0.f, a1 = 0.f, a2 = 0.f, a3 = 0.f;
    #pragma unroll 4
    for (int cc = cc0; cc < cc0 + 64; ++cc) {
        float wv = wa[o * CFULL + 256 + cc];
        a0 = fmaf(wv, catlow[cc][0], a0);
        a1 = fmaf(wv, catlow[cc][1], a1);
        a2 = fmaf(wv, catlow[cc][2], a2);
        a3 = fmaf(wv, catlow[cc][3], a3);
    }
    #pragma unroll
    for (int off = 1; off < 4; off <<= 1) {
        a0 += __shfl_xor_sync(0xffffffff, a0, off);
        a1 += __shfl_xor_sync(0xffffffff, a1, off);
        a2 += __shfl_xor_sync(0xffffffff, a2, off);
        a3 += __shfl_xor_sync(0xffffffff, a3, off);
    }
    if (part == 0) {
        float bav = ba[o];
        g_base[(b * 4 + 0) * CFULL + o] = a0 + bav;
        g_base[(b * 4 + 1) * CFULL + o] = a1 + bav;
        g_base[(b * 4 + 2) * CFULL + o] = a2 + bav;
        g_base[(b * 4 + 3) * CFULL + o] = a3 + bav;
    }
}

// ---------------------------------------------------------------------------
// Kernel 3: dwconv3x3 + transpose -> g_x1t[b][p][k] (fp16).
// ---------------------------------------------------------------------------
#define STW 137
#define DW_SMEM_BYTES (32 * 3 * STW * 4)   // 52,608

__global__ __launch_bounds__(256) void dwconvT_kernel(
    const float* __restrict__ x, const float* __restrict__ w1, const float* __restrict__ b1)
{
    extern __shared__ float stage[];   // [32 ch][3 rr][STW]
    int row = blockIdx.x & 127;
    int b   = blockIdx.x >> 7;
    int tid = threadIdx.x;
    int kl = tid & 31;
    int ng = tid >> 5;
    int c0 = ng * 16;

    if (tid < 96) {
        int ch = tid / 3, rr = tid - 3 * ch;
        stage[ch * (3 * STW) + rr * STW + 3]   = 0.f;
        stage[ch * (3 * STW) + rr * STW + 132] = 0.f;
    }

    __half* outbase = g_x1t + ((size_t)b * HW + (size_t)row * WW) * HC;

    for (int cc = 0; cc < 8; ++cc) {
        __syncthreads();
        #pragma unroll
        for (int j = 0; j < 12; ++j) {
            int i = tid + 256 * j;
            int c4 = i & 31;
            int g3 = i >> 5;
            int ch = g3 / 3;
            int rr = g3 - 3 * ch;
            int gr = row + rr - 1;
            float4 v = make_float4(0.f, 0.f, 0.f, 0.f);
            if (gr >= 0 && gr < HH)
                v = *reinterpret_cast<const float4*>(
                    x + ((size_t)(b * CFULL + cc * 32 + ch)) * HW + gr * WW + c4 * 4);
            float* sp = stage + ch * (3 * STW) + rr * STW + 4 + c4 * 4;
            sp[0] = v.x; sp[1] = v.y; sp[2] = v.z; sp[3] = v.w;
        }
        __syncthreads();
        int k = cc * 32 + kl;
        const float* wp = w1 + k * 9;
        float w00 = wp[0], w01 = wp[1], w02 = wp[2];
        float w10 = wp[3], w11 = wp[4], w12 = wp[5];
        float w20 = wp[6], w21 = wp[7], w22 = wp[8];
        float bias = b1[k];

        float rv[3][18];
        const float* sb = stage + kl * (3 * STW);
        #pragma unroll
        for (int rr = 0; rr < 3; ++rr) {
            #pragma unroll
            for (int i = 0; i < 18; ++i)
                rv[rr][i] = sb[rr * STW + 3 + c0 + i];
        }
        #pragma unroll
        for (int c = 0; c < 16; ++c) {
            float acc = bias;
            acc = fmaf(w00, rv[0][c],     acc);
            acc = fmaf(w01, rv[0][c + 1], acc);
            acc = fmaf(w02, rv[0][c + 2], acc);
            acc = fmaf(w10, rv[1][c],     acc);
            acc = fmaf(w11, rv[1][c + 1], acc);
            acc = fmaf(w12, rv[1][c + 2], acc);
            acc = fmaf(w20, rv[2][c],     acc);
            acc = fmaf(w21, rv[2][c + 1], acc);
            acc = fmaf(w22, rv[2][c + 2], acc);
            outbase[(size_t)(c0 + c) * HC + k] = __float2half_rn(acc);
        }
    }
}

// ---------------------------------------------------------------------------
// Kernel 4: fp16 GEMM (m16n8k16, full ldmatrix, cp.async double buffer),
// fp32 accumulate, direct epilogue (R8 style).
// A = g_wa_h[m][k], B = g_x1t[n][k], both K-major fp16. D = A * B^T.
// ---------------------------------------------------------------------------
__device__ __forceinline__ float gelu_exact(float v) {
    return 0.5f * v * (1.0f + erff(v * 0.70710678118654752f));
}
__device__ __forceinline__ void mma_f16(float (&d)[4], const uint32_t (&a)[4],
                                        uint32_t b0, uint32_t b1) {
    asm volatile(
        "mma.sync.aligned.m16n8k16.row.col.f32.f16.f16.f32 "
        "{%0,%1,%2,%3}, {%4,%5,%6,%7}, {%8,%9}, {%0,%1,%2,%3};"
        : "+f"(d[0]), "+f"(d[1]), "+f"(d[2]), "+f"(d[3])
        : "r"(a[0]), "r"(a[1]), "r"(a[2]), "r"(a[3]), "r"(b0), "r"(b1));
}
__device__ __forceinline__ void cp_async16(uint32_t dst, const void* src) {
    asm volatile("cp.async.cg.shared.global [%0], [%1], 16;" :: "r"(dst), "l"(src));
}
__device__ __forceinline__ void ldsm4(uint32_t (&r)[4], uint32_t addr) {
    asm volatile("ldmatrix.sync.aligned.m8n8.x4.shared.b16 {%0,%1,%2,%3}, [%4];"
                 : "=r"(r[0]), "=r"(r[1]), "=r"(r[2]), "=r"(r[3]) : "r"(addr));
}

#define BM 128
#define BN 128
#define BK 32
#define HSTR 40                            // halves per smem row (80B: conflict-free)
#define TIL_H (128 * HSTR)                 // halves per tile per stage = 5120
#define GEMM_SMEM_BYTES (4 * TIL_H * 2)    // 40,960

__global__ __launch_bounds__(256, 2) void gemm_gelu_kernel(
    const float* __restrict__ x, float* __restrict__ out)
{
    extern __shared__ __half hsm[];
    // layout: As [2][128][HSTR] halves, then Bs [2][128][HSTR]
    uint32_t as_base = (uint32_t)__cvta_generic_to_shared(hsm);
    uint32_t bs_base = as_base + 2 * TIL_H * 2;

    int m0 = blockIdx.x * BM;              // m-block fastest: B-tile L2 reuse
    int bx = blockIdx.y;                   // image row; n0 = bx*128
    int b  = blockIdx.z;
    int tid = threadIdx.x;
    int lane = tid & 31, warp = tid >> 5;
    int warpM = warp & 3;
    int warpN = warp >> 2;

    const __half* x1b = g_x1t + ((size_t)b * HW + (size_t)bx * WW) * HC;  // [n][256]
    int n0 = bx * BN;

    // cp.async: 128 rows x 4 chunks (8 halves) per tile = 512 chunks, 2/thread
    int rowi[2], kci[2];
    #pragma unroll
    for (int j = 0; j < 2; ++j) {
        int idx = tid + 256 * j;
        rowi[j] = idx >> 2;
        kci[j]  = (idx & 3) * 8;
    }

    auto load_stage = [&](int k0, int s) {
        #pragma unroll
        for (int j = 0; j < 2; ++j) {
            const __half* srcA = g_wa_h + (size_t)(m0 + rowi[j]) * HC + k0 + kci[j];
            uint32_t dstA = as_base + (s * TIL_H + rowi[j] * HSTR + kci[j]) * 2;
            cp_async16(dstA, srcA);
            const __half* srcB = x1b + (size_t)rowi[j] * HC + k0 + kci[j];
            uint32_t dstB = bs_base + (s * TIL_H + rowi[j] * HSTR + kci[j]) * 2;
            cp_async16(dstB, srcB);
        }
        asm volatile("cp.async.commit_group;" ::: "memory");
    };

    // ldmatrix per-lane offsets (halves)
    int j4 = lane >> 3;
    int a_row = ((j4 & 1) * 8) + (lane & 7);
    int a_kc  = (j4 >> 1) * 8;
    int b_row = ((j4 >> 1) * 8) + (lane & 7);
    int b_kc  = (j4 & 1) * 8;
    int aoff0 = (warpM * 32 +  0 + a_row) * HSTR + a_kc;
    int aoff1 = (warpM * 32 + 16 + a_row) * HSTR + a_kc;
    int boff[4];
    #pragma unroll
    for (int ntp = 0; ntp < 4; ++ntp)
        boff[ntp] = (warpN * 64 + ntp * 16 + b_row) * HSTR + b_kc;

    float acc[2][8][4] = {};

    load_stage(0, 0);

    #pragma unroll 1
    for (int it = 0; it < HC / BK; ++it) {
        asm volatile("cp.async.wait_group 0;" ::: "memory");
        __syncthreads();
        if (it < HC / BK - 1) load_stage((it + 1) * BK, (it + 1) & 1);

        int s = it & 1;
        uint32_t aB = as_base + s * TIL_H * 2;
        uint32_t bB = bs_base + s * TIL_H * 2;

        #pragma unroll
        for (int ks = 0; ks < 2; ++ks) {        // two k16 steps per BK=32
            uint32_t af[2][4];
            ldsm4(af[0], aB + (aoff0 + ks * 16) * 2);
            ldsm4(af[1], aB + (aoff1 + ks * 16) * 2);
            #pragma unroll
            for (int ntp = 0; ntp < 4; ++ntp) {
                uint32_t bb[4];
                ldsm4(bb, bB + (boff[ntp] + ks * 16) * 2);
                mma_f16(acc[0][2 * ntp    ], af[0], bb[0], bb[1]);
                mma_f16(acc[1][2 * ntp    ], af[1], bb[0], bb[1]);
                mma_f16(acc[0][2 * ntp + 1], af[0], bb[2], bb[3]);
                mma_f16(acc[1][2 * ntp + 1], af[1], bb[2], bb[3]);
            }
        }
    }

    // Epilogue (direct, R8 style): +base, exact GELU, gate by x, store.
    int q = ((bx >= 64) ? 2 : 0) + warpN;
    const float* basep = g_base + (b * 4 + q) * CFULL;

    #pragma unroll
    for (int mt = 0; mt < 2; ++mt) {
        int mrow0 = m0 + warpM * 32 + mt * 16 + (lane >> 2);
        int mrow1 = mrow0 + 8;
        float bs0 = basep[mrow0];
        float bs1 = basep[mrow1];
        #pragma unroll
        for (int nt = 0; nt < 8; ++nt) {
            int n = n0 + warpN * 64 + nt * 8 + (lane & 3) * 2;
            size_t off0 = ((size_t)(b * CFULL + mrow0)) * HW + n;
            size_t off1 = ((size_t)(b * CFULL + mrow1)) * HW + n;
            float2 xv0 = *reinterpret_cast<const float2*>(x + off0);
            float2 xv1 = *reinterpret_cast<const float2*>(x + off1);
            float2 r0, r1;
            r0.x = gelu_exact(acc[mt][nt][0] + bs0) * xv0.x;
            r0.y = gelu_exact(acc[mt][nt][1] + bs0) * xv0.y;
            r1.x = gelu_exact(acc[mt][nt][2] + bs1) * xv1.x;
            r1.y = gelu_exact(acc[mt][nt][3] + bs1) * xv1.y;
            *reinterpret_cast<float2*>(out + off0) = r0;
            *reinterpret_cast<float2*>(out + off1) = r1;
        }
    }
}

// ---------------------------------------------------------------------------
extern "C" void kernel_launch(void* const* d_in, const int* in_sizes, int n_in,
                              void* d_out, int out_size) {
    const float* x  = (const float*)d_in[0];
    const float* w1 = (const float*)d_in[1];
    const float* b1 = (const float*)d_in[2];
    const float* w2 = (const float*)d_in[3];
    const float* b2 = (const float*)d_in[4];
    const float* w3 = (const float*)d_in[5];
    const float* b3 = (const float*)d_in[6];
    const float* w4 = (const float*)d_in[7];
    const float* b4 = (const float*)d_in[8];
    const float* wa = (const float*)d_in[9];
    const float* ba = (const float*)d_in[10];
    float* out = (float*)d_out;

    cudaFuncSetAttribute(dwconvT_kernel,
                         cudaFuncAttributeMaxDynamicSharedMemorySize, DW_SMEM_BYTES);
    cudaFuncSetAttribute(gemm_gelu_kernel,
                         cudaFuncAttributeMaxDynamicSharedMemorySize, GEMM_SMEM_BYTES);

    // Fork-join: waconv+pool+base on a side stream, dwconvT on the main
    // (captured) stream, join before the gemm.
    cudaStream_t side;
    cudaStreamCreateWithFlags(&side, cudaStreamNonBlocking);
    cudaEvent_t eFork, eJoin;
    cudaEventCreateWithFlags(&eFork, cudaEventDisableTiming);
    cudaEventCreateWithFlags(&eJoin, cudaEventDisableTiming);

    cudaEventRecord(eFork, 0);
    cudaStreamWaitEvent(side, eFork, 0);

    waconv_kernel<<<512, 256, 0, side>>>(wa);
    pool_kernel<<<BATCH * HC * 4, 256, 0, side>>>(x);
    base_kernel<<<16, 512, 0, side>>>(w2, b2, w3, b3, w4, b4, wa, ba);
    cudaEventRecord(eJoin, side);

    dwconvT_kernel<<<BATCH * HH, 256, DW_SMEM_BYTES>>>(x, w1, b1);

    cudaStreamWaitEvent(0, eJoin, 0);
    gemm_gelu_kernel<<<dim3(CFULL / BM, HH, BATCH), 256, GEMM_SMEM_BYTES>>>(x, out);
}